// round 7
// baseline (speedup 1.0000x reference)
#include <cuda_runtime.h>
#include <cuda_bf16.h>
#include <math.h>
#include <stdint.h>

#define NN 10000
#define NE 160000
#define NB 10
#define RN 100
#define WN 704
#define NCH 11
#define EB 128        /* edges per CTA */
#define KP 112        /* padded K for mma (101 -> 112) */
#define KG 128        /* padded K in global BT */

#define SQ3    1.7320508075688772f
#define ISQ3   0.5773502691896258f
#define SQ75   2.7386127875258306f
#define C_SC   0.25f
#define C_V0   0.35355339059327373f
#define C_CG   0.20412414523193152f
#define I24    0.20412414523193152f
#define I32    0.17677669529663687f
#define I8     0.35355339059327373f
#define I16    0.25f
#define THIRD  0.3333333333333333f

__device__ float g_rbf[NE*NB];
__device__ float g_sh1[NE*3];
__device__ float g_s[NN*16];
__device__ float g_v[NN*24];
__device__ float g_aggs[NN*24];
__device__ float g_aggv[NN*96];
__device__ uint16_t g_bthi[4*WN*KG];
__device__ uint16_t g_btlo[4*WN*KG];

/* ---- smem layout (bytes), 1 CTA / SM ----
   WBUF: 2 slots x 128x65 f32 = 2x33280 (prologue overlays hh/hl = 57344)
   COL  @66560 (512)
   FEAT @67072 (128x77x4 = 39424; prologue overlays rwsm 4400)
   B    @106496 (2 slots x 2 var x 16384 = 65536)                      */
#define OFF_WBUF 0
#define OFF_HH   0
#define OFF_HL   28672
#define OFF_COL  66560
#define OFF_FEAT 67072
#define OFF_B    106496
#define SM_TOT   172032
#define FST 77
#define WSLOT 8320   /* floats per wbuf slot */

/* named barriers: Bfull=1+b, Bfree=3+b, Wfull=5+b, Wfree=7+b */
#define NBAR_SYNC(id)   asm volatile("bar.sync %0, 512;"::"r"(id):"memory")
#define NBAR_ARRIVE(id) asm volatile("bar.arrive %0, 512;"::"r"(id):"memory")

__device__ __forceinline__ uint32_t smem_u32(const void* p){
    uint32_t a; asm("{ .reg .u64 t; cvta.to.shared.u64 t, %1; cvt.u32.u64 %0, t; }":"=r"(a):"l"(p)); return a;
}
__device__ __forceinline__ void cpa16(uint32_t dst, const void* src){
    asm volatile("cp.async.ca.shared.global [%0], [%1], 16;"::"r"(dst),"l"(src):"memory");
}
__device__ __forceinline__ void cp_commit(){ asm volatile("cp.async.commit_group;":::"memory"); }
__device__ __forceinline__ void cp_wait0(){ asm volatile("cp.async.wait_group 0;":::"memory"); }
__device__ __forceinline__ void cp_wait1(){ asm volatile("cp.async.wait_group 1;":::"memory"); }
__device__ __forceinline__ void ldsm4(uint32_t* r, uint32_t a){
    asm volatile("ldmatrix.sync.aligned.m8n8.x4.shared.b16 {%0,%1,%2,%3}, [%4];"
        :"=r"(r[0]),"=r"(r[1]),"=r"(r[2]),"=r"(r[3]):"r"(a));
}
__device__ __forceinline__ void mma16816(float* d, const uint32_t* a, uint32_t b0, uint32_t b1){
    asm volatile("mma.sync.aligned.m16n8k16.row.col.f32.bf16.bf16.f32 "
        "{%0,%1,%2,%3}, {%4,%5,%6,%7}, {%8,%9}, {%0,%1,%2,%3};"
        : "+f"(d[0]),"+f"(d[1]),"+f"(d[2]),"+f"(d[3])
        : "r"(a[0]),"r"(a[1]),"r"(a[2]),"r"(a[3]),"r"(b0),"r"(b1));
}

/* ---------------- geometry ---------------- */
__global__ void geom_kernel(const float* __restrict__ pos, const int* __restrict__ row, const int* __restrict__ col){
    int e = blockIdx.x*256 + threadIdx.x;
    if (e >= NE) return;
    int r = row[e], c = col[e];
    float vx = pos[3*r]-pos[3*c], vy = pos[3*r+1]-pos[3*c+1], vz = pos[3*r+2]-pos[3*c+2];
    float len = sqrtf(vx*vx+vy*vy+vz*vz+1e-12f);
    float inv = 1.0f/len;
    g_sh1[3*e]=SQ3*vx*inv; g_sh1[3*e+1]=SQ3*vy*inv; g_sh1[3*e+2]=SQ3*vz*inv;
    const float step = 10.0f/9.0f;
#pragma unroll
    for (int k=0;k<NB;k++){ float d = len - (float)k*step; g_rbf[e*NB+k] = expf(-0.405f*d*d); }
}

/* ---------------- init ---------------- */
__global__ void init_kernel(const float* __restrict__ x, const float* __restrict__ ew){
    int idx = blockIdx.x*blockDim.x + threadIdx.x;
    int nt = gridDim.x*blockDim.x;
    if (idx < NN*16){
        int n = idx>>4, t = idx&15;
        float a = 0.f;
#pragma unroll
        for (int k=0;k<8;k++) a += x[n*8+k]*ew[k*16+t];
        g_s[idx] = a*I8;
    }
    for (int i=idx;i<NN*24;i+=nt){ g_v[i]=0.f; g_aggs[i]=0.f; }
    for (int i=idx;i<NN*96;i+=nt) g_aggv[i]=0.f;
}

/* ---------------- one-time fc_w -> BT bf16 hi/lo ---------------- */
__global__ void conv_fcw(const float* __restrict__ fcw, const float* __restrict__ fcb){
    int idx = blockIdx.x*256 + threadIdx.x;
    if (idx >= 4*WN*KG) return;
    int k = idx & (KG-1);
    int n = (idx >> 7) % WN;
    int l = idx / (WN*KG);
    float v = 0.f;
    if (k < 100)       v = fcw[(size_t)(l*RN + k)*WN + n];
    else if (k == 100) v = fcb[l*WN + n];
    __nv_bfloat16 hi = __float2bfloat16(v);
    __nv_bfloat16 lo = __float2bfloat16(v - __bfloat162float(hi));
    g_bthi[idx] = *(uint16_t*)&hi;
    g_btlo[idx] = *(uint16_t*)&lo;
}

/* ---------------- warp-specialized fused HMMA message kernel ---------------- */
__global__ void __launch_bounds__(512, 1)
msg_kernel(int l, const int* __restrict__ row, const int* __restrict__ col,
           const float* __restrict__ rw, const float* __restrict__ rb){
    extern __shared__ char smem[];
    uint32_t sbase = smem_u32(smem);
    int tid = threadIdx.x;
    int wid = tid>>5, lane = tid&31;
    int e0 = blockIdx.x*EB;
    int mtid = tid - 256;                 /* msg role index (>=0 for warps 8-15) */

    uint16_t* hh = (uint16_t*)(smem + OFF_HH);
    uint16_t* hl = (uint16_t*)(smem + OFF_HL);
    float*    wbuf = (float*)(smem + OFF_WBUF);
    int*      colsm = (int*)(smem + OFF_COL);
    float*    featf = (float*)(smem + OFF_FEAT);
    float*    rwsm  = featf;

    /* msg threads: kick off B chunk 0 staging */
    if (mtid >= 0){
        const uint16_t* srcs[2] = { g_bthi + (size_t)l*WN*KG, g_btlo + (size_t)l*WN*KG };
#pragma unroll
        for (int i=0;i<8;i++){
            int cid = mtid + i*256;
            int var = cid >> 10;
            int n   = (cid & 1023) >> 4;
            int j   = cid & 15;
            cpa16(sbase + OFF_B + var*16384 + ((n*16 + (j ^ (n&7)))<<4),
                  srcs[var] + ((size_t)n*KG + j*8));
        }
        cp_commit();
    }

    /* zero hh/hl, load radial weights (all 512) */
    {
        uint32_t* z = (uint32_t*)(smem + OFF_HH);
        for (int i=tid;i<14336;i+=512) z[i] = 0;
        for (int i=tid;i<1100;i+=512) rwsm[i] = (i<1000) ? rw[l*1000+i] : rb[l*100+i-1000];
    }
    __syncthreads();

    /* h compute: thread = (edge, quarter), 25 r each */
    {
        int e = tid>>2, q = tid&3, eg = e0 + e;
        float rbf[NB];
#pragma unroll
        for (int k=0;k<NB;k++) rbf[k] = g_rbf[eg*NB+k];
        int r0 = q*25;
        for (int r=r0; r<r0+25; r++){
            float a = rwsm[1000+r];
#pragma unroll
            for (int k=0;k<NB;k++) a += rbf[k]*rwsm[k*RN+r];
            a = fmaxf(a, 0.f);
            __nv_bfloat16 bh = __float2bfloat16(a);
            __nv_bfloat16 bl = __float2bfloat16(a - __bfloat162float(bh));
            hh[e*KP + r] = *(uint16_t*)&bh;
            hl[e*KP + r] = *(uint16_t*)&bl;
        }
        if (q == 0) hh[e*KP + 100] = 0x3F80;
    }
    __syncthreads();

    if (tid < 256){
        /* ================= GEMM role: warps 0-7, strip = wid ================= */
        int g = lane>>2, tig = lane&3;
        int mi = lane>>3, rowin = lane&7;
        uint32_t ahh[28], ahl[28];
        {
            int ra = wid*16 + g;
#pragma unroll
            for (int ks=0;ks<7;ks++){
                int k0 = ks*16 + tig*2;
                ahh[ks*4+0] = *(uint32_t*)&hh[ra*KP + k0];
                ahh[ks*4+1] = *(uint32_t*)&hh[(ra+8)*KP + k0];
                ahh[ks*4+2] = *(uint32_t*)&hh[ra*KP + k0+8];
                ahh[ks*4+3] = *(uint32_t*)&hh[(ra+8)*KP + k0+8];
                ahl[ks*4+0] = *(uint32_t*)&hl[ra*KP + k0];
                ahl[ks*4+1] = *(uint32_t*)&hl[(ra+8)*KP + k0];
                ahl[ks*4+2] = *(uint32_t*)&hl[ra*KP + k0+8];
                ahl[ks*4+3] = *(uint32_t*)&hl[(ra+8)*KP + k0+8];
            }
        }
        __syncthreads();

        for (int c=0;c<NCH;c++){
            int b = c&1;
            NBAR_SYNC(1+b);                    /* B(c) ready */
            float accf[32];
#pragma unroll
            for (int i=0;i<32;i++) accf[i] = 0.f;
            uint32_t bb = sbase + OFF_B + b*32768;
#pragma unroll
            for (int q4=0;q4<4;q4++){
#pragma unroll
                for (int nf=0;nf<8;nf++){
                    uint32_t off = ((nf*8 + rowin)*16 + ((q4*4+mi) ^ rowin)) << 4;
                    uint32_t bh4[4], bl4[4];
                    ldsm4(bh4, bb + off);
                    ldsm4(bl4, bb + 16384 + off);
                    float* A = accf + nf*4;
                    mma16816(A, ahh + (2*q4)*4, bh4[0], bh4[1]);
                    mma16816(A, ahh + (2*q4)*4, bl4[0], bl4[1]);
                    mma16816(A, ahl + (2*q4)*4, bh4[0], bh4[1]);
                    if (q4 < 3){
                        mma16816(A, ahh + (2*q4+1)*4, bh4[2], bh4[3]);
                        mma16816(A, ahh + (2*q4+1)*4, bl4[2], bl4[3]);
                        mma16816(A, ahl + (2*q4+1)*4, bh4[2], bh4[3]);
                    }
                }
            }
            NBAR_ARRIVE(3+b);                  /* B slot free */
            if (c >= 2) NBAR_SYNC(7+b);        /* wbuf slot free */
            {
                float* wb = wbuf + b*WSLOT;
                int r0 = wid*16 + g;
#pragma unroll
                for (int nf=0;nf<8;nf++){
                    int cl = nf*8 + tig*2;
                    wb[r0*65 + cl]       = accf[nf*4+0];
                    wb[r0*65 + cl+1]     = accf[nf*4+1];
                    wb[(r0+8)*65 + cl]   = accf[nf*4+2];
                    wb[(r0+8)*65 + cl+1] = accf[nf*4+3];
                }
            }
            NBAR_ARRIVE(5+b);                  /* wbuf slot full */
        }
    } else {
        /* ================= MSG role: warps 8-15 ================= */
        /* features + col (mtid < 128 -> one edge each) */
        if (mtid < 128){
            int e = mtid, eg = e0 + e;
            int rr = row[eg];
            colsm[e] = col[eg];
            float* F = featf + e*FST;
#pragma unroll
            for (int t=0;t<16;t++) F[t] = g_s[rr*16+t];
#pragma unroll
            for (int i=0;i<24;i++) F[16+i] = g_v[rr*24+i];
            float s1x = g_sh1[eg*3], s1y = g_sh1[eg*3+1], s1z = g_sh1[eg*3+2];
            F[72]=s1x; F[73]=s1y; F[74]=s1z;
            float ux=s1x*ISQ3, uy=s1y*ISQ3, uz=s1z*ISQ3;
#pragma unroll
            for (int u=0;u<8;u++){
                float vx=F[16+u*3], vy=F[17+u*3], vz=F[18+u*3];
                float dot = ux*vx+uy*vy+uz*vz;
                F[40+u] = SQ3*dot;
                F[48+u*3] = SQ75*(dot*ux - vx*THIRD);
                F[49+u*3] = SQ75*(dot*uy - vy*THIRD);
                F[50+u*3] = SQ75*(dot*uz - vz*THIRD);
            }
        }
        __syncthreads();

        int me = mtid>>1, h8 = (mtid&1)*8;
        const float* F = featf + me*FST;
        float s1x = F[72], s1y = F[73], s1z = F[74];
        int cn = colsm[me];
        float acc0[8], acc1[8];

        for (int c=0;c<NCH;c++){
            int b = c&1;
            if (c+1 < NCH){
                int ns = (c+1)&1;
                if (c+1 >= 2) NBAR_SYNC(3+ns);         /* B slot free */
                const uint16_t* srcs[2] = { g_bthi + (size_t)l*WN*KG + (size_t)(c+1)*64*KG,
                                            g_btlo + (size_t)l*WN*KG + (size_t)(c+1)*64*KG };
                uint32_t db = sbase + OFF_B + ns*32768;
#pragma unroll
                for (int i=0;i<8;i++){
                    int cid = mtid + i*256;
                    int var = cid >> 10;
                    int n   = (cid & 1023) >> 4;
                    int j   = cid & 15;
                    cpa16(db + var*16384 + ((n*16 + (j ^ (n&7)))<<4),
                          srcs[var] + ((size_t)n*KG + j*8));
                }
                cp_commit();
                cp_wait1();                            /* B(c) landed */
                NBAR_ARRIVE(1+b);
            } else {
                cp_wait0();
                NBAR_ARRIVE(1+b);
            }
            NBAR_SYNC(5+b);                            /* wbuf(c) full */
            const float* W = wbuf + b*WSLOT + me*65;

            if (c < 4){
                if (c == 0){
#pragma unroll
                    for (int t=0;t<8;t++) acc0[t] = 0.f;
                }
#pragma unroll
                for (int u=0;u<4;u++){
                    float s = F[c*4+u];
#pragma unroll
                    for (int t=0;t<8;t++) acc0[t] += W[u*16 + h8 + t]*s;
                }
                if (c == 3){
#pragma unroll
                    for (int t=0;t<8;t++) atomicAdd(&g_aggs[cn*24 + h8 + t], acc0[t]*C_SC);
                }
            } else if (c < 8){
                if (c == 4){
#pragma unroll
                    for (int t=0;t<8;t++) acc1[t] = 0.f;
                }
#pragma unroll
                for (int u=0;u<4;u++){
                    float s = F[(c-4)*4+u];
#pragma unroll
                    for (int t=0;t<8;t++) acc1[t] += W[u*16 + h8 + t]*s;
                }
                if (c == 7){
#pragma unroll
                    for (int t=0;t<8;t++){
                        float f = acc1[t]*C_SC;
                        int tg = h8 + t;
                        atomicAdd(&g_aggv[cn*96 + tg*3 + 0], f*s1x);
                        atomicAdd(&g_aggv[cn*96 + tg*3 + 1], f*s1y);
                        atomicAdd(&g_aggv[cn*96 + tg*3 + 2], f*s1z);
                    }
                }
            } else if (c == 8){
#pragma unroll
                for (int jj=0;jj<4;jj++){
                    int j = (h8>>1) + jj;
                    float ax=0.f, ay=0.f, az=0.f;
#pragma unroll
                    for (int u=0;u<8;u++){
                        float w = W[u*8+j];
                        ax += w*F[16+u*3]; ay += w*F[17+u*3]; az += w*F[18+u*3];
                    }
                    atomicAdd(&g_aggv[cn*96 + (16+j)*3 + 0], ax*C_V0);
                    atomicAdd(&g_aggv[cn*96 + (16+j)*3 + 1], ay*C_V0);
                    atomicAdd(&g_aggv[cn*96 + (16+j)*3 + 2], az*C_V0);
                }
            } else if (c == 9){
#pragma unroll
                for (int jj=0;jj<4;jj++){
                    int j = (h8>>1) + jj;
                    float a = 0.f;
#pragma unroll
                    for (int u=0;u<8;u++) a += W[u*8+j]*F[40+u];
                    atomicAdd(&g_aggs[cn*24 + 16 + j], a*C_CG);
                }
            } else {
#pragma unroll
                for (int jj=0;jj<4;jj++){
                    int j = (h8>>1) + jj;
                    float ax=0.f, ay=0.f, az=0.f;
#pragma unroll
                    for (int u=0;u<8;u++){
                        float w = W[u*8+j];
                        ax += w*F[48+u*3]; ay += w*F[49+u*3]; az += w*F[50+u*3];
                    }
                    atomicAdd(&g_aggv[cn*96 + (24+j)*3 + 0], ax*C_CG);
                    atomicAdd(&g_aggv[cn*96 + (24+j)*3 + 1], ay*C_CG);
                    atomicAdd(&g_aggv[cn*96 + (24+j)*3 + 2], az*C_CG);
                }
            }
            NBAR_ARRIVE(7+b);                          /* wbuf slot free */
        }
    }
}

/* ---------------- node updates ---------------- */
__global__ void upd_s(int l, const float* __restrict__ lws){
    int idx = blockIdx.x*256 + threadIdx.x;
    if (idx >= NN*16) return;
    int n = idx>>4, t = idx&15;
    float a = 0.f;
#pragma unroll
    for (int u=0;u<24;u++) a += g_aggs[n*24+u]*lws[l*384+u*16+t];
    g_s[idx] += a*I24;
}
__global__ void upd_v(int l, const float* __restrict__ lwv){
    int idx = blockIdx.x*256 + threadIdx.x;
    if (idx >= NN*8) return;
    int n = idx>>3, w = idx&7;
    float ax=0.f, ay=0.f, az=0.f;
#pragma unroll
    for (int u=0;u<32;u++){
        float lw = lwv[l*256+u*8+w];
        ax += g_aggv[n*96+u*3+0]*lw;
        ay += g_aggv[n*96+u*3+1]*lw;
        az += g_aggv[n*96+u*3+2]*lw;
    }
    g_v[n*24+w*3+0] += ax*I32;
    g_v[n*24+w*3+1] += ay*I32;
    g_v[n*24+w*3+2] += az*I32;
}
__global__ void zagg(){
    int i = blockIdx.x*256 + threadIdx.x;
    if (i < NN*24) g_aggs[i] = 0.f;
    if (i < NN*96) g_aggv[i] = 0.f;
}

/* ---------------- output ---------------- */
__global__ void out_kernel(const float* __restrict__ ow, float* __restrict__ out){
    int idx = blockIdx.x*256 + threadIdx.x;
    if (idx >= NN*8) return;
    int n = idx>>3, t = idx&7;
    float a = 0.f;
#pragma unroll
    for (int k=0;k<16;k++) a += g_s[n*16+k]*ow[k*8+t];
    out[idx] = a*I16;
}

/* ---------------- launch ---------------- */
extern "C" void kernel_launch(void* const* d_in, const int* in_sizes, int n_in,
                              void* d_out, int out_size){
    const float *x=0, *pos=0, *embed_w=0, *radial_w=0, *radial_b=0;
    const float *fc_w=0, *fc_b=0, *lin_ws=0, *lin_wv=0, *out_w=0;
    const int *ei=0;
    for (int i=0;i<n_in;i++){
        switch (in_sizes[i]){
            case 80000:  x=(const float*)d_in[i]; break;
            case 30000:  pos=(const float*)d_in[i]; break;
            case 4000:   radial_w=(const float*)d_in[i]; break;
            case 400:    radial_b=(const float*)d_in[i]; break;
            case 281600: fc_w=(const float*)d_in[i]; break;
            case 2816:   fc_b=(const float*)d_in[i]; break;
            case 1536:   lin_ws=(const float*)d_in[i]; break;
            case 1024:   lin_wv=(const float*)d_in[i]; break;
            case 320000: ei=(const int*)d_in[i]; break;
            case 128:
                if (!embed_w) embed_w=(const float*)d_in[i];
                else          out_w=(const float*)d_in[i];
                break;
        }
    }
    const int* row = ei;
    const int* col = ei + NE;
    float* out = (float*)d_out;

    cudaFuncSetAttribute(msg_kernel, cudaFuncAttributeMaxDynamicSharedMemorySize, SM_TOT);

    conv_fcw<<<(4*WN*KG + 255)/256, 256>>>(fc_w, fc_b);
    geom_kernel<<<(NE+255)/256, 256>>>(pos, row, col);
    init_kernel<<<(NN*16+255)/256, 256>>>(x, embed_w);

    for (int l=0;l<4;l++){
        msg_kernel<<<NE/EB, 512, SM_TOT>>>(l, row, col, radial_w, radial_b);
        upd_s<<<(NN*16+255)/256, 256>>>(l, lin_ws);
        upd_v<<<(NN*8+255)/256, 256>>>(l, lin_wv);
        zagg<<<(NN*96+255)/256, 256>>>();
    }
    out_kernel<<<(NN*8+255)/256, 256>>>(out_w, out);
}

// round 8
// speedup vs baseline: 2.2067x; 2.2067x over previous
#include <cuda_runtime.h>
#include <cuda_fp16.h>
#include <math.h>
#include <stdint.h>

#define NN 10000
#define NE 160000
#define NB 10
#define RN 100
#define WN 704
#define NCH 11
#define EB 128
#define KP 112
#define KG 128

#define SQ3    1.7320508075688772f
#define ISQ3   0.5773502691896258f
#define SQ75   2.7386127875258306f
#define C_SC   0.25f
#define C_V0   0.35355339059327373f
#define C_CG   0.20412414523193152f
#define I24    0.20412414523193152f
#define I32    0.17677669529663687f
#define I8     0.35355339059327373f
#define I16    0.25f
#define THIRD  0.3333333333333333f

__device__ float g_rbf[NE*NB];
__device__ float g_sh1[NE*3];
__device__ float g_s[NN*16];
__device__ float g_v[NN*24];
__device__ float g_aggs[NN*24];
__device__ float g_aggv[NN*96];
__device__ uint16_t g_bt[4*WN*KG];   /* fc_w^T fp16, [l][n][k] padded */

/* ---- smem layout ---- */
#define OFF_HH   0        /* fp16 h [128][112] = 28672 */
#define OFF_COL  28672    /* 128 ints */
#define OFF_FEAT 29184    /* 128*77*4 = 39424 (rwsm overlay in prologue) */
#define OFF_B    68608    /* 2 slots x 16384 */
#define SM_TOT   101376
#define FST 77

__device__ __forceinline__ uint32_t smem_u32(const void* p){
    uint32_t a; asm("{ .reg .u64 t; cvta.to.shared.u64 t, %1; cvt.u32.u64 %0, t; }":"=r"(a):"l"(p)); return a;
}
__device__ __forceinline__ void cpa16(uint32_t dst, const void* src){
    asm volatile("cp.async.ca.shared.global [%0], [%1], 16;"::"r"(dst),"l"(src):"memory");
}
__device__ __forceinline__ void cp_commit(){ asm volatile("cp.async.commit_group;":::"memory"); }
__device__ __forceinline__ void cp_wait0(){ asm volatile("cp.async.wait_group 0;":::"memory"); }
__device__ __forceinline__ void ldsm4(uint32_t* r, uint32_t a){
    asm volatile("ldmatrix.sync.aligned.m8n8.x4.shared.b16 {%0,%1,%2,%3}, [%4];"
        :"=r"(r[0]),"=r"(r[1]),"=r"(r[2]),"=r"(r[3]):"r"(a));
}
__device__ __forceinline__ void mma16816(float* d, const uint32_t* a, uint32_t b0, uint32_t b1){
    asm volatile("mma.sync.aligned.m16n8k16.row.col.f32.f16.f16.f32 "
        "{%0,%1,%2,%3}, {%4,%5,%6,%7}, {%8,%9}, {%0,%1,%2,%3};"
        : "+f"(d[0]),"+f"(d[1]),"+f"(d[2]),"+f"(d[3])
        : "r"(a[0]),"r"(a[1]),"r"(a[2]),"r"(a[3]),"r"(b0),"r"(b1));
}

/* ---------------- geometry ---------------- */
__global__ void geom_kernel(const float* __restrict__ pos, const int* __restrict__ row, const int* __restrict__ col){
    int e = blockIdx.x*256 + threadIdx.x;
    if (e >= NE) return;
    int r = row[e], c = col[e];
    float vx = pos[3*r]-pos[3*c], vy = pos[3*r+1]-pos[3*c+1], vz = pos[3*r+2]-pos[3*c+2];
    float len = sqrtf(vx*vx+vy*vy+vz*vz+1e-12f);
    float inv = 1.0f/len;
    g_sh1[3*e]=SQ3*vx*inv; g_sh1[3*e+1]=SQ3*vy*inv; g_sh1[3*e+2]=SQ3*vz*inv;
    const float step = 10.0f/9.0f;
#pragma unroll
    for (int k=0;k<NB;k++){ float d = len - (float)k*step; g_rbf[e*NB+k] = expf(-0.405f*d*d); }
}

/* ---------------- init ---------------- */
__global__ void init_kernel(const float* __restrict__ x, const float* __restrict__ ew){
    int idx = blockIdx.x*blockDim.x + threadIdx.x;
    int nt = gridDim.x*blockDim.x;
    if (idx < NN*16){
        int n = idx>>4, t = idx&15;
        float a = 0.f;
#pragma unroll
        for (int k=0;k<8;k++) a += x[n*8+k]*ew[k*16+t];
        g_s[idx] = a*I8;
    }
    for (int i=idx;i<NN*24;i+=nt){ g_v[i]=0.f; g_aggs[i]=0.f; }
    for (int i=idx;i<NN*96;i+=nt) g_aggv[i]=0.f;
}

/* ---------------- one-time fc_w -> BT fp16 ---------------- */
__global__ void conv_fcw(const float* __restrict__ fcw, const float* __restrict__ fcb){
    int idx = blockIdx.x*256 + threadIdx.x;
    if (idx >= 4*WN*KG) return;
    int k = idx & (KG-1);
    int n = (idx >> 7) % WN;
    int l = idx / (WN*KG);
    float v = 0.f;
    if (k < 100)       v = fcw[(size_t)(l*RN + k)*WN + n];
    else if (k == 100) v = fcb[l*WN + n];
    __half h = __float2half_rn(v);
    g_bt[idx] = *(uint16_t*)&h;
}

/* ---------------- fused HMMA message kernel ---------------- */
__global__ void __launch_bounds__(256, 2)
msg_kernel(int l, const int* __restrict__ row, const int* __restrict__ col,
           const float* __restrict__ rw, const float* __restrict__ rb){
    extern __shared__ char smem[];
    uint32_t sbase = smem_u32(smem);
    int tid = threadIdx.x;
    int wid = tid>>5, lane = tid&31;
    int g = lane>>2, tig = lane&3;
    int mi = lane>>3, rowin = lane&7;
    int e0 = blockIdx.x*EB;

    uint16_t* hh = (uint16_t*)(smem + OFF_HH);
    int*      colsm = (int*)(smem + OFF_COL);
    float*    featf = (float*)(smem + OFF_FEAT);
    float*    rwsm  = featf;

    /* kick off B chunk 0 staging (1024 x 16B) */
    {
        const uint16_t* src = g_bt + (size_t)l*WN*KG;
#pragma unroll
        for (int i=0;i<4;i++){
            int cid = tid + i*256;
            int n = cid>>4, j = cid&15;
            cpa16(sbase + OFF_B + ((n*16 + (j ^ (n&7)))<<4), src + (size_t)n*KG + j*8);
        }
        cp_commit();
    }

    /* load radial weights, zero hh pad rows 101..111 */
    for (int i=tid;i<1100;i+=256) rwsm[i] = (i<1000) ? rw[l*1000+i] : rb[l*100+i-1000];
    for (int i=tid;i<1408;i+=256){
        int e = i/11, r = 101 + (i - e*11);
        hh[e*KP + r] = 0;
    }
    __syncthreads();

    /* h compute: thread = (edge, half), 50 r each, fp16 */
    {
        int e = tid>>1, half = tid&1, eg = e0 + e;
        float rbf[NB];
#pragma unroll
        for (int k=0;k<NB;k++) rbf[k] = g_rbf[eg*NB+k];
        int r0h = half*50;
        for (int r=r0h; r<r0h+50; r++){
            float a = rwsm[1000+r];
#pragma unroll
            for (int k=0;k<NB;k++) a += rbf[k]*rwsm[k*RN+r];
            a = fmaxf(a, 0.f);
            __half hv = __float2half_rn(a);
            hh[e*KP + r] = *(uint16_t*)&hv;
        }
        if (half == 0) hh[e*KP + 100] = 0x3C00;   /* bias row: A = 1.0 fp16 */
    }
    __syncthreads();

    /* A fragment preload (fp16, 28 regs) for strip wid: rows r0 = wid*16+g, r0+8 */
    uint32_t ahh[28];
    int r0 = wid*16 + g;
    {
#pragma unroll
        for (int ks=0;ks<7;ks++){
            int k0 = ks*16 + tig*2;
            ahh[ks*4+0] = *(uint32_t*)&hh[r0*KP + k0];
            ahh[ks*4+1] = *(uint32_t*)&hh[(r0+8)*KP + k0];
            ahh[ks*4+2] = *(uint32_t*)&hh[r0*KP + k0+8];
            ahh[ks*4+3] = *(uint32_t*)&hh[(r0+8)*KP + k0+8];
        }
    }
    __syncthreads();   /* hh dead; FEAT(rwsm) dead after this point */

    /* features + col (thread = edge for tid<128); overwrites rwsm overlay */
    if (tid < EB){
        int e = tid, eg = e0 + e;
        int rr = row[eg];
        colsm[e] = col[eg];
        float* F = featf + e*FST;
#pragma unroll
        for (int t=0;t<16;t++) F[t] = g_s[rr*16+t];
#pragma unroll
        for (int i=0;i<24;i++) F[16+i] = g_v[rr*24+i];
        float s1x = g_sh1[eg*3], s1y = g_sh1[eg*3+1], s1z = g_sh1[eg*3+2];
        F[72]=s1x; F[73]=s1y; F[74]=s1z;
        float ux=s1x*ISQ3, uy=s1y*ISQ3, uz=s1z*ISQ3;
#pragma unroll
        for (int u=0;u<8;u++){
            float vx=F[16+u*3], vy=F[17+u*3], vz=F[18+u*3];
            float dot = ux*vx+uy*vy+uz*vz;
            F[40+u] = SQ3*dot;
            F[48+u*3] = SQ75*(dot*ux - vx*THIRD);
            F[49+u*3] = SQ75*(dot*uy - vy*THIRD);
            F[50+u*3] = SQ75*(dot*uz - vz*THIRD);
        }
    }
    cp_wait0();
    __syncthreads();   /* B(0) visible, features ready */

    const float* F0 = featf + r0*FST;
    const float* F1 = featf + (r0+8)*FST;
    int cn0 = colsm[r0], cn1 = colsm[r0+8];
    float m0a[4], m0b[4], m1a[4], m1b[4];

#pragma unroll
    for (int c=0;c<NCH;c++){
        /* prefetch chunk c+1 (slot (c+1)&1 was last read for chunk c-1, synced) */
        if (c+1 < NCH){
            const uint16_t* src = g_bt + ((size_t)l*WN + (c+1)*64)*KG;
            uint32_t db = sbase + OFF_B + ((c+1)&1)*16384;
#pragma unroll
            for (int i=0;i<4;i++){
                int cid = tid + i*256;
                int n = cid>>4, j = cid&15;
                cpa16(db + ((n*16 + (j ^ (n&7)))<<4), src + (size_t)n*KG + j*8);
            }
            cp_commit();
        }

        /* GEMM: 8 nf x 7 ksteps, single fp16 pass */
        float accf[32];
#pragma unroll
        for (int i=0;i<32;i++) accf[i] = 0.f;
        {
            uint32_t bb = sbase + OFF_B + (c&1)*16384;
#pragma unroll
            for (int q4=0;q4<4;q4++){
#pragma unroll
                for (int nf=0;nf<8;nf++){
                    uint32_t bm[4];
                    ldsm4(bm, bb + (((nf*8 + rowin)*16 + ((q4*4+mi) ^ rowin)) << 4));
                    mma16816(accf + nf*4, ahh + (2*q4)*4, bm[0], bm[1]);
                    if (q4 < 3)
                        mma16816(accf + nf*4, ahh + (2*q4+1)*4, bm[2], bm[3]);
                }
            }
        }

        /* messages from register accumulators */
        if (c < 4){
            if (c == 0){
#pragma unroll
                for (int s=0;s<4;s++){ m0a[s]=0.f; m0b[s]=0.f; }
            }
#pragma unroll
            for (int nf=0;nf<8;nf++){
                float s0 = F0[c*4 + (nf>>1)];
                float s1 = F1[c*4 + (nf>>1)];
                int sl = (nf&1)*2;
                m0a[sl+0] += accf[nf*4+0]*s0;
                m0a[sl+1] += accf[nf*4+1]*s0;
                m0b[sl+0] += accf[nf*4+2]*s1;
                m0b[sl+1] += accf[nf*4+3]*s1;
            }
            if (c == 3){
#pragma unroll
                for (int s=0;s<4;s++){
                    int t = (s>>1)*8 + tig*2 + (s&1);
                    atomicAdd(&g_aggs[cn0*24 + t], m0a[s]*C_SC);
                    atomicAdd(&g_aggs[cn1*24 + t], m0b[s]*C_SC);
                }
            }
        } else if (c < 8){
            if (c == 4){
#pragma unroll
                for (int s=0;s<4;s++){ m1a[s]=0.f; m1b[s]=0.f; }
            }
#pragma unroll
            for (int nf=0;nf<8;nf++){
                float s0 = F0[(c-4)*4 + (nf>>1)];
                float s1 = F1[(c-4)*4 + (nf>>1)];
                int sl = (nf&1)*2;
                m1a[sl+0] += accf[nf*4+0]*s0;
                m1a[sl+1] += accf[nf*4+1]*s0;
                m1b[sl+0] += accf[nf*4+2]*s1;
                m1b[sl+1] += accf[nf*4+3]*s1;
            }
            if (c == 7){
#pragma unroll
                for (int s=0;s<4;s++){
                    int t = (s>>1)*8 + tig*2 + (s&1);
                    float fa = m1a[s]*C_SC, fb = m1b[s]*C_SC;
#pragma unroll
                    for (int d=0;d<3;d++){
                        atomicAdd(&g_aggv[cn0*96 + t*3 + d], fa*F0[72+d]);
                        atomicAdd(&g_aggv[cn1*96 + t*3 + d], fb*F1[72+d]);
                    }
                }
            }
        } else if (c == 8){
#pragma unroll
            for (int p=0;p<2;p++){
                int j = tig*2 + p;
                float ax0=0.f,ay0=0.f,az0=0.f, ax1=0.f,ay1=0.f,az1=0.f;
#pragma unroll
                for (int nf=0;nf<8;nf++){
                    float w0 = accf[nf*4+p],  w1 = accf[nf*4+2+p];
                    ax0 += w0*F0[16+nf*3]; ay0 += w0*F0[17+nf*3]; az0 += w0*F0[18+nf*3];
                    ax1 += w1*F1[16+nf*3]; ay1 += w1*F1[17+nf*3]; az1 += w1*F1[18+nf*3];
                }
                atomicAdd(&g_aggv[cn0*96 + (16+j)*3 + 0], ax0*C_V0);
                atomicAdd(&g_aggv[cn0*96 + (16+j)*3 + 1], ay0*C_V0);
                atomicAdd(&g_aggv[cn0*96 + (16+j)*3 + 2], az0*C_V0);
                atomicAdd(&g_aggv[cn1*96 + (16+j)*3 + 0], ax1*C_V0);
                atomicAdd(&g_aggv[cn1*96 + (16+j)*3 + 1], ay1*C_V0);
                atomicAdd(&g_aggv[cn1*96 + (16+j)*3 + 2], az1*C_V0);
            }
        } else if (c == 9){
#pragma unroll
            for (int p=0;p<2;p++){
                int j = tig*2 + p;
                float a0=0.f, a1=0.f;
#pragma unroll
                for (int nf=0;nf<8;nf++){
                    a0 += accf[nf*4+p]*F0[40+nf];
                    a1 += accf[nf*4+2+p]*F1[40+nf];
                }
                atomicAdd(&g_aggs[cn0*24 + 16 + j], a0*C_CG);
                atomicAdd(&g_aggs[cn1*24 + 16 + j], a1*C_CG);
            }
        } else {
#pragma unroll
            for (int p=0;p<2;p++){
                int j = tig*2 + p;
                float ax0=0.f,ay0=0.f,az0=0.f, ax1=0.f,ay1=0.f,az1=0.f;
#pragma unroll
                for (int nf=0;nf<8;nf++){
                    float w0 = accf[nf*4+p],  w1 = accf[nf*4+2+p];
                    ax0 += w0*F0[48+nf*3]; ay0 += w0*F0[49+nf*3]; az0 += w0*F0[50+nf*3];
                    ax1 += w1*F1[48+nf*3]; ay1 += w1*F1[49+nf*3]; az1 += w1*F1[50+nf*3];
                }
                atomicAdd(&g_aggv[cn0*96 + (24+j)*3 + 0], ax0*C_CG);
                atomicAdd(&g_aggv[cn0*96 + (24+j)*3 + 1], ay0*C_CG);
                atomicAdd(&g_aggv[cn0*96 + (24+j)*3 + 2], az0*C_CG);
                atomicAdd(&g_aggv[cn1*96 + (24+j)*3 + 0], ax1*C_CG);
                atomicAdd(&g_aggv[cn1*96 + (24+j)*3 + 1], ay1*C_CG);
                atomicAdd(&g_aggv[cn1*96 + (24+j)*3 + 2], az1*C_CG);
            }
        }

        cp_wait0();
        __syncthreads();   /* B(c+1) visible to all; slot c&1 free for c+2 prefetch */
    }
}

/* ---------------- node updates ---------------- */
__global__ void upd_s(int l, const float* __restrict__ lws){
    int idx = blockIdx.x*256 + threadIdx.x;
    if (idx >= NN*16) return;
    int n = idx>>4, t = idx&15;
    float a = 0.f;
#pragma unroll
    for (int u=0;u<24;u++) a += g_aggs[n*24+u]*lws[l*384+u*16+t];
    g_s[idx] += a*I24;
}
__global__ void upd_v(int l, const float* __restrict__ lwv){
    int idx = blockIdx.x*256 + threadIdx.x;
    if (idx >= NN*8) return;
    int n = idx>>3, w = idx&7;
    float ax=0.f, ay=0.f, az=0.f;
#pragma unroll
    for (int u=0;u<32;u++){
        float lw = lwv[l*256+u*8+w];
        ax += g_aggv[n*96+u*3+0]*lw;
        ay += g_aggv[n*96+u*3+1]*lw;
        az += g_aggv[n*96+u*3+2]*lw;
    }
    g_v[n*24+w*3+0] += ax*I32;
    g_v[n*24+w*3+1] += ay*I32;
    g_v[n*24+w*3+2] += az*I32;
}
__global__ void zagg(){
    int i = blockIdx.x*256 + threadIdx.x;
    if (i < NN*24) g_aggs[i] = 0.f;
    if (i < NN*96) g_aggv[i] = 0.f;
}

/* ---------------- output ---------------- */
__global__ void out_kernel(const float* __restrict__ ow, float* __restrict__ out){
    int idx = blockIdx.x*256 + threadIdx.x;
    if (idx >= NN*8) return;
    int n = idx>>3, t = idx&7;
    float a = 0.f;
#pragma unroll
    for (int k=0;k<16;k++) a += g_s[n*16+k]*ow[k*8+t];
    out[idx] = a*I16;
}

/* ---------------- launch ---------------- */
extern "C" void kernel_launch(void* const* d_in, const int* in_sizes, int n_in,
                              void* d_out, int out_size){
    const float *x=0, *pos=0, *embed_w=0, *radial_w=0, *radial_b=0;
    const float *fc_w=0, *fc_b=0, *lin_ws=0, *lin_wv=0, *out_w=0;
    const int *ei=0;
    for (int i=0;i<n_in;i++){
        switch (in_sizes[i]){
            case 80000:  x=(const float*)d_in[i]; break;
            case 30000:  pos=(const float*)d_in[i]; break;
            case 4000:   radial_w=(const float*)d_in[i]; break;
            case 400:    radial_b=(const float*)d_in[i]; break;
            case 281600: fc_w=(const float*)d_in[i]; break;
            case 2816:   fc_b=(const float*)d_in[i]; break;
            case 1536:   lin_ws=(const float*)d_in[i]; break;
            case 1024:   lin_wv=(const float*)d_in[i]; break;
            case 320000: ei=(const int*)d_in[i]; break;
            case 128:
                if (!embed_w) embed_w=(const float*)d_in[i];
                else          out_w=(const float*)d_in[i];
                break;
        }
    }
    const int* row = ei;
    const int* col = ei + NE;
    float* out = (float*)d_out;

    cudaFuncSetAttribute(msg_kernel, cudaFuncAttributeMaxDynamicSharedMemorySize, SM_TOT);

    conv_fcw<<<(4*WN*KG + 255)/256, 256>>>(fc_w, fc_b);
    geom_kernel<<<(NE+255)/256, 256>>>(pos, row, col);
    init_kernel<<<(NN*16+255)/256, 256>>>(x, embed_w);

    for (int l=0;l<4;l++){
        msg_kernel<<<NE/EB, 256, SM_TOT>>>(l, row, col, radial_w, radial_b);
        upd_s<<<(NN*16+255)/256, 256>>>(l, lin_ws);
        upd_v<<<(NN*8+255)/256, 256>>>(l, lin_wv);
        zagg<<<(NN*96+255)/256, 256>>>();
    }
    out_kernel<<<(NN*8+255)/256, 256>>>(out_w, out);
}

// round 9
// speedup vs baseline: 2.5823x; 1.1702x over previous
#include <cuda_runtime.h>
#include <cuda_fp16.h>
#include <math.h>
#include <stdint.h>

#define NN 10000
#define NE 160000
#define NB 10
#define RN 100
#define WN 704
#define NCH 11
#define EB 128
#define KP 112
#define KG 128

#define SQ3    1.7320508075688772f
#define ISQ3   0.5773502691896258f
#define SQ75   2.7386127875258306f
#define C_SC   0.25f
#define C_V0   0.35355339059327373f
#define C_CG   0.20412414523193152f
#define I24    0.20412414523193152f
#define I32    0.17677669529663687f
#define I8     0.35355339059327373f
#define I16    0.25f
#define THIRD  0.3333333333333333f

__device__ float g_rbf[NE*NB];
__device__ float g_sh1[NE*3];
__device__ float g_s[NN*16];
__device__ float g_v[NN*24];
__device__ float g_aggs[NN*24];
__device__ float g_aggv[NN*128];     /* [N][32][4] padded for float4 atomics */
__device__ uint16_t g_bt[4*WN*KG];   /* fc_w^T fp16, [l][n][k] padded */

/* ---- smem layout ---- */
#define OFF_HH   0
#define OFF_COL  28672
#define OFF_FEAT 29184
#define OFF_B    68608
#define SM_TOT   101376
#define FST 77

__device__ __forceinline__ uint32_t smem_u32(const void* p){
    uint32_t a; asm("{ .reg .u64 t; cvta.to.shared.u64 t, %1; cvt.u32.u64 %0, t; }":"=r"(a):"l"(p)); return a;
}
__device__ __forceinline__ void cpa16(uint32_t dst, const void* src){
    asm volatile("cp.async.ca.shared.global [%0], [%1], 16;"::"r"(dst),"l"(src):"memory");
}
__device__ __forceinline__ void cp_commit(){ asm volatile("cp.async.commit_group;":::"memory"); }
__device__ __forceinline__ void cp_wait0(){ asm volatile("cp.async.wait_group 0;":::"memory"); }
__device__ __forceinline__ void ldsm4(uint32_t* r, uint32_t a){
    asm volatile("ldmatrix.sync.aligned.m8n8.x4.shared.b16 {%0,%1,%2,%3}, [%4];"
        :"=r"(r[0]),"=r"(r[1]),"=r"(r[2]),"=r"(r[3]):"r"(a));
}
__device__ __forceinline__ void mma16816(float* d, const uint32_t* a, uint32_t b0, uint32_t b1){
    asm volatile("mma.sync.aligned.m16n8k16.row.col.f32.f16.f16.f32 "
        "{%0,%1,%2,%3}, {%4,%5,%6,%7}, {%8,%9}, {%0,%1,%2,%3};"
        : "+f"(d[0]),"+f"(d[1]),"+f"(d[2]),"+f"(d[3])
        : "r"(a[0]),"r"(a[1]),"r"(a[2]),"r"(a[3]),"r"(b0),"r"(b1));
}
__device__ __forceinline__ void red2(float* p, float a, float b){
    atomicAdd((float2*)p, make_float2(a,b));
}
__device__ __forceinline__ void red4(float* p, float a, float b, float c){
    atomicAdd((float4*)p, make_float4(a,b,c,0.f));
}

/* ---------------- geometry ---------------- */
__global__ void geom_kernel(const float* __restrict__ pos, const int* __restrict__ row, const int* __restrict__ col){
    int e = blockIdx.x*256 + threadIdx.x;
    if (e >= NE) return;
    int r = row[e], c = col[e];
    float vx = pos[3*r]-pos[3*c], vy = pos[3*r+1]-pos[3*c+1], vz = pos[3*r+2]-pos[3*c+2];
    float len = sqrtf(vx*vx+vy*vy+vz*vz+1e-12f);
    float inv = 1.0f/len;
    g_sh1[3*e]=SQ3*vx*inv; g_sh1[3*e+1]=SQ3*vy*inv; g_sh1[3*e+2]=SQ3*vz*inv;
    const float step = 10.0f/9.0f;
#pragma unroll
    for (int k=0;k<NB;k++){ float d = len - (float)k*step; g_rbf[e*NB+k] = expf(-0.405f*d*d); }
}

/* ---------------- init ---------------- */
__global__ void init_kernel(const float* __restrict__ x, const float* __restrict__ ew){
    int idx = blockIdx.x*blockDim.x + threadIdx.x;
    int nt = gridDim.x*blockDim.x;
    if (idx < NN*16){
        int n = idx>>4, t = idx&15;
        float a = 0.f;
#pragma unroll
        for (int k=0;k<8;k++) a += x[n*8+k]*ew[k*16+t];
        g_s[idx] = a*I8;
    }
    for (int i=idx;i<NN*24;i+=nt){ g_v[i]=0.f; g_aggs[i]=0.f; }
    for (int i=idx;i<NN*128;i+=nt) g_aggv[i]=0.f;
}

/* ---------------- one-time fc_w -> BT fp16 ---------------- */
__global__ void conv_fcw(const float* __restrict__ fcw, const float* __restrict__ fcb){
    int idx = blockIdx.x*256 + threadIdx.x;
    if (idx >= 4*WN*KG) return;
    int k = idx & (KG-1);
    int n = (idx >> 7) % WN;
    int l = idx / (WN*KG);
    float v = 0.f;
    if (k < 100)       v = fcw[(size_t)(l*RN + k)*WN + n];
    else if (k == 100) v = fcb[l*WN + n];
    __half h = __float2half_rn(v);
    g_bt[idx] = *(uint16_t*)&h;
}

/* ---------------- fused HMMA message kernel ---------------- */
__global__ void __launch_bounds__(256, 2)
msg_kernel(int l, const int* __restrict__ row, const int* __restrict__ col,
           const float* __restrict__ rw, const float* __restrict__ rb){
    extern __shared__ char smem[];
    uint32_t sbase = smem_u32(smem);
    int tid = threadIdx.x;
    int wid = tid>>5, lane = tid&31;
    int g = lane>>2, tig = lane&3;
    int mi = lane>>3, rowin = lane&7;
    int e0 = blockIdx.x*EB;

    uint16_t* hh = (uint16_t*)(smem + OFF_HH);
    int*      colsm = (int*)(smem + OFF_COL);
    float*    featf = (float*)(smem + OFF_FEAT);
    float*    rwsm  = featf;

    /* kick off B chunk 0 staging */
    {
        const uint16_t* src = g_bt + (size_t)l*WN*KG;
#pragma unroll
        for (int i=0;i<4;i++){
            int cid = tid + i*256;
            int n = cid>>4, j = cid&15;
            cpa16(sbase + OFF_B + ((n*16 + (j ^ (n&7)))<<4), src + (size_t)n*KG + j*8);
        }
        cp_commit();
    }

    /* load radial weights, zero hh pad rows 101..111 */
    for (int i=tid;i<1100;i+=256) rwsm[i] = (i<1000) ? rw[l*1000+i] : rb[l*100+i-1000];
    for (int i=tid;i<1408;i+=256){
        int e = i/11, r = 101 + (i - e*11);
        hh[e*KP + r] = 0;
    }
    __syncthreads();

    /* h compute: thread = (edge, half), 50 r each, fp16 */
    {
        int e = tid>>1, half = tid&1, eg = e0 + e;
        float rbf[NB];
#pragma unroll
        for (int k=0;k<NB;k++) rbf[k] = g_rbf[eg*NB+k];
        int r0h = half*50;
        for (int r=r0h; r<r0h+50; r++){
            float a = rwsm[1000+r];
#pragma unroll
            for (int k=0;k<NB;k++) a += rbf[k]*rwsm[k*RN+r];
            a = fmaxf(a, 0.f);
            __half hv = __float2half_rn(a);
            hh[e*KP + r] = *(uint16_t*)&hv;
        }
        if (half == 0) hh[e*KP + 100] = 0x3C00;
    }
    __syncthreads();

    /* A fragment preload for strip wid: rows r0, r0+8 */
    uint32_t ahh[28];
    int r0 = wid*16 + g;
    {
#pragma unroll
        for (int ks=0;ks<7;ks++){
            int k0 = ks*16 + tig*2;
            ahh[ks*4+0] = *(uint32_t*)&hh[r0*KP + k0];
            ahh[ks*4+1] = *(uint32_t*)&hh[(r0+8)*KP + k0];
            ahh[ks*4+2] = *(uint32_t*)&hh[r0*KP + k0+8];
            ahh[ks*4+3] = *(uint32_t*)&hh[(r0+8)*KP + k0+8];
        }
    }
    __syncthreads();

    /* features + col (thread = edge for tid<128) */
    if (tid < EB){
        int e = tid, eg = e0 + e;
        int rr = row[eg];
        colsm[e] = col[eg];
        float* F = featf + e*FST;
#pragma unroll
        for (int t=0;t<16;t++) F[t] = g_s[rr*16+t];
#pragma unroll
        for (int i=0;i<24;i++) F[16+i] = g_v[rr*24+i];
        float s1x = g_sh1[eg*3], s1y = g_sh1[eg*3+1], s1z = g_sh1[eg*3+2];
        F[72]=s1x; F[73]=s1y; F[74]=s1z;
        float ux=s1x*ISQ3, uy=s1y*ISQ3, uz=s1z*ISQ3;
#pragma unroll
        for (int u=0;u<8;u++){
            float vx=F[16+u*3], vy=F[17+u*3], vz=F[18+u*3];
            float dot = ux*vx+uy*vy+uz*vz;
            F[40+u] = SQ3*dot;
            F[48+u*3] = SQ75*(dot*ux - vx*THIRD);
            F[49+u*3] = SQ75*(dot*uy - vy*THIRD);
            F[50+u*3] = SQ75*(dot*uz - vz*THIRD);
        }
    }
    cp_wait0();
    __syncthreads();

    const float* F0 = featf + r0*FST;
    const float* F1 = featf + (r0+8)*FST;
    int cn0 = colsm[r0], cn1 = colsm[r0+8];
    float m0a[4], m0b[4], m1a[4], m1b[4];

#pragma unroll
    for (int c=0;c<NCH;c++){
        if (c+1 < NCH){
            const uint16_t* src = g_bt + ((size_t)l*WN + (c+1)*64)*KG;
            uint32_t db = sbase + OFF_B + ((c+1)&1)*16384;
#pragma unroll
            for (int i=0;i<4;i++){
                int cid = tid + i*256;
                int n = cid>>4, j = cid&15;
                cpa16(db + ((n*16 + (j ^ (n&7)))<<4), src + (size_t)n*KG + j*8);
            }
            cp_commit();
        }

        /* GEMM: 8 nf x 7 ksteps, single fp16 pass */
        float accf[32];
#pragma unroll
        for (int i=0;i<32;i++) accf[i] = 0.f;
        {
            uint32_t bb = sbase + OFF_B + (c&1)*16384;
#pragma unroll
            for (int q4=0;q4<4;q4++){
#pragma unroll
                for (int nf=0;nf<8;nf++){
                    uint32_t bm[4];
                    ldsm4(bm, bb + (((nf*8 + rowin)*16 + ((q4*4+mi) ^ rowin)) << 4));
                    mma16816(accf + nf*4, ahh + (2*q4)*4, bm[0], bm[1]);
                    if (q4 < 3)
                        mma16816(accf + nf*4, ahh + (2*q4+1)*4, bm[2], bm[3]);
                }
            }
        }

        /* messages from register accumulators (vector atomics) */
        if (c < 4){
            if (c == 0){
#pragma unroll
                for (int s=0;s<4;s++){ m0a[s]=0.f; m0b[s]=0.f; }
            }
#pragma unroll
            for (int nf=0;nf<8;nf++){
                float s0 = F0[c*4 + (nf>>1)];
                float s1 = F1[c*4 + (nf>>1)];
                int sl = (nf&1)*2;
                m0a[sl+0] += accf[nf*4+0]*s0;
                m0a[sl+1] += accf[nf*4+1]*s0;
                m0b[sl+0] += accf[nf*4+2]*s1;
                m0b[sl+1] += accf[nf*4+3]*s1;
            }
            if (c == 3){
                red2(&g_aggs[cn0*24 + tig*2],     m0a[0]*C_SC, m0a[1]*C_SC);
                red2(&g_aggs[cn0*24 + 8 + tig*2], m0a[2]*C_SC, m0a[3]*C_SC);
                red2(&g_aggs[cn1*24 + tig*2],     m0b[0]*C_SC, m0b[1]*C_SC);
                red2(&g_aggs[cn1*24 + 8 + tig*2], m0b[2]*C_SC, m0b[3]*C_SC);
            }
        } else if (c < 8){
            if (c == 4){
#pragma unroll
                for (int s=0;s<4;s++){ m1a[s]=0.f; m1b[s]=0.f; }
            }
#pragma unroll
            for (int nf=0;nf<8;nf++){
                float s0 = F0[(c-4)*4 + (nf>>1)];
                float s1 = F1[(c-4)*4 + (nf>>1)];
                int sl = (nf&1)*2;
                m1a[sl+0] += accf[nf*4+0]*s0;
                m1a[sl+1] += accf[nf*4+1]*s0;
                m1b[sl+0] += accf[nf*4+2]*s1;
                m1b[sl+1] += accf[nf*4+3]*s1;
            }
            if (c == 7){
#pragma unroll
                for (int s=0;s<4;s++){
                    int t = (s>>1)*8 + tig*2 + (s&1);
                    float fa = m1a[s]*C_SC, fb = m1b[s]*C_SC;
                    red4(&g_aggv[cn0*128 + t*4], fa*F0[72], fa*F0[73], fa*F0[74]);
                    red4(&g_aggv[cn1*128 + t*4], fb*F1[72], fb*F1[73], fb*F1[74]);
                }
            }
        } else if (c == 8){
#pragma unroll
            for (int p=0;p<2;p++){
                int j = tig*2 + p;
                float ax0=0.f,ay0=0.f,az0=0.f, ax1=0.f,ay1=0.f,az1=0.f;
#pragma unroll
                for (int nf=0;nf<8;nf++){
                    float w0 = accf[nf*4+p],  w1 = accf[nf*4+2+p];
                    ax0 += w0*F0[16+nf*3]; ay0 += w0*F0[17+nf*3]; az0 += w0*F0[18+nf*3];
                    ax1 += w1*F1[16+nf*3]; ay1 += w1*F1[17+nf*3]; az1 += w1*F1[18+nf*3];
                }
                red4(&g_aggv[cn0*128 + (16+j)*4], ax0*C_V0, ay0*C_V0, az0*C_V0);
                red4(&g_aggv[cn1*128 + (16+j)*4], ax1*C_V0, ay1*C_V0, az1*C_V0);
            }
        } else if (c == 9){
            float a0=0.f, a1=0.f, b0=0.f, b1=0.f;
#pragma unroll
            for (int nf=0;nf<8;nf++){
                a0 += accf[nf*4+0]*F0[40+nf];
                a1 += accf[nf*4+1]*F0[40+nf];
                b0 += accf[nf*4+2]*F1[40+nf];
                b1 += accf[nf*4+3]*F1[40+nf];
            }
            red2(&g_aggs[cn0*24 + 16 + tig*2], a0*C_CG, a1*C_CG);
            red2(&g_aggs[cn1*24 + 16 + tig*2], b0*C_CG, b1*C_CG);
        } else {
#pragma unroll
            for (int p=0;p<2;p++){
                int j = tig*2 + p;
                float ax0=0.f,ay0=0.f,az0=0.f, ax1=0.f,ay1=0.f,az1=0.f;
#pragma unroll
                for (int nf=0;nf<8;nf++){
                    float w0 = accf[nf*4+p],  w1 = accf[nf*4+2+p];
                    ax0 += w0*F0[48+nf*3]; ay0 += w0*F0[49+nf*3]; az0 += w0*F0[50+nf*3];
                    ax1 += w1*F1[48+nf*3]; ay1 += w1*F1[49+nf*3]; az1 += w1*F1[50+nf*3];
                }
                red4(&g_aggv[cn0*128 + (24+j)*4], ax0*C_CG, ay0*C_CG, az0*C_CG);
                red4(&g_aggv[cn1*128 + (24+j)*4], ax1*C_CG, ay1*C_CG, az1*C_CG);
            }
        }

        cp_wait0();
        __syncthreads();
    }
}

/* ---------------- node updates (zagg folded in) ---------------- */
__global__ void upd_s(int l, const float* __restrict__ lws){
    int idx = blockIdx.x*256 + threadIdx.x;   /* grid exactly NN*16/256 */
    int n = idx>>4, t = idx&15;
    float a = 0.f;
#pragma unroll
    for (int u=0;u<24;u++) a += g_aggs[n*24+u]*lws[l*384+u*16+t];
    __syncthreads();
    g_s[idx] += a*I24;
    int base = (blockIdx.x<<4)*24;            /* 16 nodes * 24 per block */
    for (int i=threadIdx.x;i<384;i+=256) g_aggs[base+i] = 0.f;
}
__global__ void upd_v(int l, const float* __restrict__ lwv){
    int idx = blockIdx.x*256 + threadIdx.x;
    bool act = idx < NN*8;
    int n = act ? (idx>>3) : 0, w = idx&7;
    float ax=0.f, ay=0.f, az=0.f;
    if (act){
#pragma unroll
        for (int u=0;u<32;u++){
            float lw = lwv[l*256+u*8+w];
            ax += g_aggv[n*128+u*4+0]*lw;
            ay += g_aggv[n*128+u*4+1]*lw;
            az += g_aggv[n*128+u*4+2]*lw;
        }
    }
    __syncthreads();
    if (act){
        g_v[n*24+w*3+0] += ax*I32;
        g_v[n*24+w*3+1] += ay*I32;
        g_v[n*24+w*3+2] += az*I32;
    }
    int base = blockIdx.x*32*128;             /* 32 nodes * 128 per block */
    for (int i=threadIdx.x;i<4096;i+=256){
        int gidx = base+i;
        if (gidx < NN*128) g_aggv[gidx] = 0.f;
    }
}

/* ---------------- output ---------------- */
__global__ void out_kernel(const float* __restrict__ ow, float* __restrict__ out){
    int idx = blockIdx.x*256 + threadIdx.x;
    if (idx >= NN*8) return;
    int n = idx>>3, t = idx&7;
    float a = 0.f;
#pragma unroll
    for (int k=0;k<16;k++) a += g_s[n*16+k]*ow[k*8+t];
    out[idx] = a*I16;
}

/* ---------------- launch ---------------- */
extern "C" void kernel_launch(void* const* d_in, const int* in_sizes, int n_in,
                              void* d_out, int out_size){
    const float *x=0, *pos=0, *embed_w=0, *radial_w=0, *radial_b=0;
    const float *fc_w=0, *fc_b=0, *lin_ws=0, *lin_wv=0, *out_w=0;
    const int *ei=0;
    for (int i=0;i<n_in;i++){
        switch (in_sizes[i]){
            case 80000:  x=(const float*)d_in[i]; break;
            case 30000:  pos=(const float*)d_in[i]; break;
            case 4000:   radial_w=(const float*)d_in[i]; break;
            case 400:    radial_b=(const float*)d_in[i]; break;
            case 281600: fc_w=(const float*)d_in[i]; break;
            case 2816:   fc_b=(const float*)d_in[i]; break;
            case 1536:   lin_ws=(const float*)d_in[i]; break;
            case 1024:   lin_wv=(const float*)d_in[i]; break;
            case 320000: ei=(const int*)d_in[i]; break;
            case 128:
                if (!embed_w) embed_w=(const float*)d_in[i];
                else          out_w=(const float*)d_in[i];
                break;
        }
    }
    const int* row = ei;
    const int* col = ei + NE;
    float* out = (float*)d_out;

    cudaFuncSetAttribute(msg_kernel, cudaFuncAttributeMaxDynamicSharedMemorySize, SM_TOT);

    conv_fcw<<<(4*WN*KG + 255)/256, 256>>>(fc_w, fc_b);
    geom_kernel<<<(NE+255)/256, 256>>>(pos, row, col);
    init_kernel<<<(NN*16+255)/256, 256>>>(x, embed_w);

    for (int l=0;l<4;l++){
        msg_kernel<<<NE/EB, 256, SM_TOT>>>(l, row, col, radial_w, radial_b);
        upd_s<<<NN*16/256, 256>>>(l, lin_ws);
        upd_v<<<(NN*8+255)/256, 256>>>(l, lin_wv);
    }
    out_kernel<<<(NN*8+255)/256, 256>>>(out_w, out);
}